// round 6
// baseline (speedup 1.0000x reference)
#include <cuda_runtime.h>
#include <cuda_bf16.h>

#define NN 65536
#define EE 1048576
#define DD 64
#define CC 101
#define BN_EPS 1e-5f

// ---------------- scratch (device globals; no allocation allowed) -------------
__device__ float g_Y0[NN * DD];
__device__ float g_Y1[NN * DD];
__device__ float g_A0[NN * DD];
__device__ float g_A1[NN * DD];
__device__ float g_H [NN * DD];
__device__ float g_X1[NN * DD];
__device__ float g_X2[NN * DD];
__device__ float g_X3[NN * DD];
__device__ int    g_cnt[NN];
__device__ int    g_ptr[NN + 1];
__device__ int    g_esrc[EE];
__device__ double g_stat[3][128];   // per-conv: [0:64) col sums, [64:128) col sumsq

// ---------------- CSR build --------------------------------------------------
__global__ void k_init() {
    int i = blockIdx.x * blockDim.x + threadIdx.x;
    if (i < NN) g_cnt[i] = 0;
    if (i < 3 * 128) ((double*)g_stat)[i] = 0.0;
}

__global__ void k_count(const int* __restrict__ dst) {
    int e = (blockIdx.x * blockDim.x + threadIdx.x) * 2;
    if (e < EE) {
        int2 d = *(const int2*)(dst + e);
        atomicAdd(&g_cnt[d.x], 1);
        atomicAdd(&g_cnt[d.y], 1);
    }
}

__global__ void k_scan() {
    __shared__ int ps[1024];
    int t = threadIdx.x;
    int base = t << 6;
    int s = 0;
#pragma unroll 8
    for (int j = 0; j < 64; j++) s += g_cnt[base + j];
    ps[t] = s;
    __syncthreads();
    for (int off = 1; off < 1024; off <<= 1) {
        int add = 0;
        if (t >= off) add = ps[t - off];
        __syncthreads();
        ps[t] += add;
        __syncthreads();
    }
    int incl = ps[t];
    int run = incl - s;     // exclusive prefix for this thread's chunk
#pragma unroll 8
    for (int j = 0; j < 64; j++) {
        int c = g_cnt[base + j];
        g_ptr[base + j] = run;
        run += c;
        g_cnt[base + j] = 0;   // reuse as fill cursor in scatter
    }
    if (t == 1023) g_ptr[NN] = incl;
}

__global__ void k_scatter(const int* __restrict__ src, const int* __restrict__ dst) {
    int e = (blockIdx.x * blockDim.x + threadIdx.x) * 2;
    if (e < EE) {
        int2 d = *(const int2*)(dst + e);
        int2 s = *(const int2*)(src + e);
        int p0 = atomicAdd(&g_cnt[d.x], 1);
        g_esrc[g_ptr[d.x] + p0] = s.x;
        int p1 = atomicAdd(&g_cnt[d.y], 1);
        g_esrc[g_ptr[d.y] + p1] = s.y;
    }
}

// ---------------- N x 64 @ 64 x 64 GEMM (warp per row, shuffle-broadcast) ----
template <int STATS>
__global__ void k_lin64(const float* __restrict__ in, const float* __restrict__ W,
                        float* __restrict__ out, int statIdx) {
    __shared__ float Ws[64 * 64];
    __shared__ float ssum[64], ssq[64];
    int t = threadIdx.x;
    for (int i = t; i < 4096; i += blockDim.x) Ws[i] = W[i];
    if (STATS && t < 64) { ssum[t] = 0.f; ssq[t] = 0.f; }
    __syncthreads();
    int warp = t >> 5, lane = t & 31;
    float s0 = 0.f, s1 = 0.f, q0 = 0.f, q1 = 0.f;
    int row0 = blockIdx.x * 64 + warp;
#pragma unroll
    for (int r = 0; r < 8; r++) {
        int row = row0 + r * 8;
        float r0v = in[row * 64 + lane];
        float r1v = in[row * 64 + 32 + lane];
        float a0 = 0.f, a1 = 0.f;
#pragma unroll
        for (int j = 0; j < 32; j++) {
            float v = __shfl_sync(0xffffffffu, r0v, j);
            a0 = fmaf(v, Ws[j * 64 + lane], a0);
            a1 = fmaf(v, Ws[j * 64 + 32 + lane], a1);
        }
#pragma unroll
        for (int j = 0; j < 32; j++) {
            float v = __shfl_sync(0xffffffffu, r1v, j);
            a0 = fmaf(v, Ws[(32 + j) * 64 + lane], a0);
            a1 = fmaf(v, Ws[(32 + j) * 64 + 32 + lane], a1);
        }
        out[row * 64 + lane] = a0;
        out[row * 64 + 32 + lane] = a1;
        if (STATS) { s0 += a0; s1 += a1; q0 += a0 * a0; q1 += a1 * a1; }
    }
    if (STATS) {
        atomicAdd(&ssum[lane], s0);       atomicAdd(&ssum[lane + 32], s1);
        atomicAdd(&ssq[lane], q0);        atomicAdd(&ssq[lane + 32], q1);
        __syncthreads();
        if (t < 64) {
            atomicAdd(&g_stat[statIdx][t],      (double)ssum[t]);
            atomicAdd(&g_stat[statIdx][64 + t], (double)ssq[t]);
        }
    }
}

// ---------------- gather-max: warp per node, float2 per lane, 2x unroll ------
template <int DUAL>
__global__ void k_gather(const float* __restrict__ y0, const float* __restrict__ y1,
                         const float* __restrict__ pos,
                         const float* __restrict__ Wp0,   // rows 64,65 of Wl (2 x 64)
                         const float* __restrict__ Wp1,
                         float* __restrict__ a0out, float* __restrict__ a1out) {
    int warp = threadIdx.x >> 5, lane = threadIdx.x & 31;
    int node = blockIdx.x * 8 + warp;

    const float2* Y0 = (const float2*)y0;
    const float2* Y1 = (const float2*)y1;
    const float2* P  = (const float2*)pos;

    float2 wx0 = ((const float2*)Wp0)[lane];
    float2 wy0 = ((const float2*)(Wp0 + 64))[lane];
    float2 wx1 = make_float2(0.f, 0.f), wy1 = make_float2(0.f, 0.f);
    if (DUAL) {
        wx1 = ((const float2*)Wp1)[lane];
        wy1 = ((const float2*)(Wp1 + 64))[lane];
    }

    float2 pi = P[node];
    float2 m0 = Y0[node * 32 + lane];               // self-loop (dpos = 0)
    float2 m1 = make_float2(0.f, 0.f);
    if (DUAL) m1 = Y1[node * 32 + lane];

    int b = g_ptr[node], e = g_ptr[node + 1];
    int k = b;
    for (; k + 2 <= e; k += 2) {
        int s0 = g_esrc[k];
        int s1 = g_esrc[k + 1];
        float2 p0 = P[s0];
        float2 p1 = P[s1];
        float2 v0 = Y0[s0 * 32 + lane];
        float2 v1 = Y0[s1 * 32 + lane];
        float dx0 = p0.x - pi.x, dy0 = p0.y - pi.y;
        float dx1 = p1.x - pi.x, dy1 = p1.y - pi.y;
        v0.x = fmaf(dx0, wx0.x, fmaf(dy0, wy0.x, v0.x));
        v0.y = fmaf(dx0, wx0.y, fmaf(dy0, wy0.y, v0.y));
        v1.x = fmaf(dx1, wx0.x, fmaf(dy1, wy0.x, v1.x));
        v1.y = fmaf(dx1, wx0.y, fmaf(dy1, wy0.y, v1.y));
        m0.x = fmaxf(m0.x, fmaxf(v0.x, v1.x));
        m0.y = fmaxf(m0.y, fmaxf(v0.y, v1.y));
        if (DUAL) {
            float2 u0 = Y1[s0 * 32 + lane];
            float2 u1 = Y1[s1 * 32 + lane];
            u0.x = fmaf(dx0, wx1.x, fmaf(dy0, wy1.x, u0.x));
            u0.y = fmaf(dx0, wx1.y, fmaf(dy0, wy1.y, u0.y));
            u1.x = fmaf(dx1, wx1.x, fmaf(dy1, wy1.x, u1.x));
            u1.y = fmaf(dx1, wx1.y, fmaf(dy1, wy1.y, u1.y));
            m1.x = fmaxf(m1.x, fmaxf(u0.x, u1.x));
            m1.y = fmaxf(m1.y, fmaxf(u0.y, u1.y));
        }
    }
    if (k < e) {
        int s = g_esrc[k];
        float2 psrc = P[s];
        float dx = psrc.x - pi.x, dy = psrc.y - pi.y;
        float2 v = Y0[s * 32 + lane];
        v.x = fmaf(dx, wx0.x, fmaf(dy, wy0.x, v.x));
        v.y = fmaf(dx, wx0.y, fmaf(dy, wy0.y, v.y));
        m0.x = fmaxf(m0.x, v.x);
        m0.y = fmaxf(m0.y, v.y);
        if (DUAL) {
            float2 u = Y1[s * 32 + lane];
            u.x = fmaf(dx, wx1.x, fmaf(dy, wy1.x, u.x));
            u.y = fmaf(dx, wx1.y, fmaf(dy, wy1.y, u.y));
            m1.x = fmaxf(m1.x, u.x);
            m1.y = fmaxf(m1.y, u.y);
        }
    }
    ((float2*)a0out)[node * 32 + lane] = m0;
    if (DUAL) ((float2*)a1out)[node * 32 + lane] = m1;
}

// ---------------- BN (biased var) + ReLU -------------------------------------
__global__ void k_bnrelu(const float* __restrict__ h, const float* __restrict__ g,
                         const float* __restrict__ b, float* __restrict__ out, int statIdx) {
    int i = blockIdx.x * blockDim.x + threadIdx.x;   // N*64 threads
    int col = i & 63;
    double sum = g_stat[statIdx][col];
    double sq  = g_stat[statIdx][64 + col];
    double mu_d = sum / (double)NN;
    double var_d = sq / (double)NN - mu_d * mu_d;
    float mu = (float)mu_d;
    float inv = rsqrtf(fmaxf((float)var_d, 0.f) + BN_EPS);
    float v = (h[i] - mu) * inv * g[col] + b[col];
    out[i] = fmaxf(v, 0.f);
}

// ---------------- head GEMM: N x 64 @ 64 x K + bias --------------------------
template <int K>
__global__ void k_head(const float* __restrict__ in, const float* __restrict__ W,
                       const float* __restrict__ bias, float* __restrict__ out) {
    __shared__ float Ws[64 * K];
    int t = threadIdx.x;
    for (int i = t; i < 64 * K; i += blockDim.x) Ws[i] = W[i];
    __syncthreads();
    int warp = t >> 5, lane = t & 31;
    int row = blockIdx.x * 8 + warp;
    constexpr int NC = (K + 31) / 32;
    float acc[NC];
#pragma unroll
    for (int c = 0; c < NC; c++) {
        int col = lane + 32 * c;
        acc[c] = (col < K) ? bias[col] : 0.f;
    }
    float r0v = in[row * 64 + lane];
    float r1v = in[row * 64 + 32 + lane];
#pragma unroll
    for (int j = 0; j < 32; j++) {
        float v = __shfl_sync(0xffffffffu, r0v, j);
#pragma unroll
        for (int c = 0; c < NC; c++) {
            int col = lane + 32 * c;
            if (col < K) acc[c] = fmaf(v, Ws[j * K + col], acc[c]);
        }
    }
#pragma unroll
    for (int j = 0; j < 32; j++) {
        float v = __shfl_sync(0xffffffffu, r1v, j);
#pragma unroll
        for (int c = 0; c < NC; c++) {
            int col = lane + 32 * c;
            if (col < K) acc[c] = fmaf(v, Ws[(32 + j) * K + col], acc[c]);
        }
    }
#pragma unroll
    for (int c = 0; c < NC; c++) {
        int col = lane + 32 * c;
        if (col < K) out[row * K + col] = acc[c];
    }
}

// ---------------- launch -----------------------------------------------------
extern "C" void kernel_launch(void* const* d_in, const int* in_sizes, int n_in,
                              void* d_out, int out_size) {
    const float* x   = (const float*)d_in[0];
    const float* pos = (const float*)d_in[1];
    const int*   ei  = (const int*)  d_in[2];
    const float* W11 = (const float*)d_in[3];
    const float* W12 = (const float*)d_in[4];
    const float* g1  = (const float*)d_in[5];
    const float* b1  = (const float*)d_in[6];
    const float* W21 = (const float*)d_in[7];
    const float* W22 = (const float*)d_in[8];
    const float* g2  = (const float*)d_in[9];
    const float* b2  = (const float*)d_in[10];
    const float* W31 = (const float*)d_in[11];
    const float* W32 = (const float*)d_in[12];
    const float* g3  = (const float*)d_in[13];
    const float* b3  = (const float*)d_in[14];
    const float* Wr1 = (const float*)d_in[15];
    const float* Wr2 = (const float*)d_in[16];
    const float* br2 = (const float*)d_in[17];
    const float* Wc1 = (const float*)d_in[18];
    const float* Wc2 = (const float*)d_in[19];
    const float* bc2 = (const float*)d_in[20];
    const float* Wo1 = (const float*)d_in[21];
    const float* Wo2 = (const float*)d_in[22];
    const float* bo2 = (const float*)d_in[23];
    float* out = (float*)d_out;

    float* out_cls = out;                     // N x 101
    float* out_reg = out + (size_t)NN * CC;   // N x 4
    float* out_obj = out_reg + (size_t)NN * 4;// N x 1

    const int* src = ei;
    const int* dst = ei + EE;

    // device symbol addresses for scratch (pure queries; no stream ops)
    float *Y0, *Y1, *A0, *A1, *H, *X1, *X2, *X3;
    cudaGetSymbolAddress((void**)&Y0, g_Y0);
    cudaGetSymbolAddress((void**)&Y1, g_Y1);
    cudaGetSymbolAddress((void**)&A0, g_A0);
    cudaGetSymbolAddress((void**)&A1, g_A1);
    cudaGetSymbolAddress((void**)&H,  g_H);
    cudaGetSymbolAddress((void**)&X1, g_X1);
    cudaGetSymbolAddress((void**)&X2, g_X2);
    cudaGetSymbolAddress((void**)&X3, g_X3);

    const int TB = 256;

    // ---- CSR build (per launch; deterministic result: max is order-invariant)
    k_init<<<(NN + TB - 1) / TB, TB>>>();
    k_count<<<EE / (2 * TB), TB>>>(dst);
    k_scan<<<1, 1024>>>();
    k_scatter<<<EE / (2 * TB), TB>>>(src, dst);

    const int GL = NN / 64;     // lin64 grid
    const int GG = NN / 8;      // gather / head grid

    // ---- conv1: x -> x1
    k_lin64<0><<<GL, TB>>>(x, W11, Y0, 0);
    k_gather<0><<<GG, TB>>>(Y0, Y0, pos, W11 + 64 * 64, W11 + 64 * 64, A0, A0);
    k_lin64<1><<<GL, TB>>>(A0, W12, H, 0);
    k_bnrelu<<<(NN * DD) / TB, TB>>>(H, g1, b1, X1, 0);

    // ---- conv2 + conv3 (shared input x1, fused gather)
    k_lin64<0><<<GL, TB>>>(X1, W21, Y0, 0);
    k_lin64<0><<<GL, TB>>>(X1, W31, Y1, 0);
    k_gather<1><<<GG, TB>>>(Y0, Y1, pos, W21 + 64 * 64, W31 + 64 * 64, A0, A1);
    k_lin64<1><<<GL, TB>>>(A0, W22, H, 1);
    k_bnrelu<<<(NN * DD) / TB, TB>>>(H, g2, b2, X2, 1);
    k_lin64<1><<<GL, TB>>>(A1, W32, H, 2);
    k_bnrelu<<<(NN * DD) / TB, TB>>>(H, g3, b3, X3, 2);

    // ---- reg head (from x2)
    k_lin64<0><<<GL, TB>>>(X2, Wr1, Y0, 0);
    k_gather<0><<<GG, TB>>>(Y0, Y0, pos, Wr1 + 64 * 64, Wr1 + 64 * 64, A0, A0);
    k_head<4><<<GG, TB>>>(A0, Wr2, br2, out_reg);

    // ---- cls + obj heads (shared input x3, fused gather)
    k_lin64<0><<<GL, TB>>>(X3, Wc1, Y0, 0);
    k_lin64<0><<<GL, TB>>>(X3, Wo1, Y1, 0);
    k_gather<1><<<GG, TB>>>(Y0, Y1, pos, Wc1 + 64 * 64, Wo1 + 64 * 64, A0, A1);
    k_head<CC><<<GG, TB>>>(A0, Wc2, bc2, out_cls);
    k_head<1><<<GG, TB>>>(A1, Wo2, bo2, out_obj);
}

// round 10
// speedup vs baseline: 1.3265x; 1.3265x over previous
#include <cuda_runtime.h>
#include <cuda_bf16.h>

#define NN 65536
#define EE 1048576
#define DD 64
#define CC 101
#define BN_EPS 1e-5f

// ---------------- scratch (device globals; no allocation allowed) -------------
__device__ float g_Y0[NN * DD];
__device__ float g_Y1[NN * DD];
__device__ float g_A0[NN * DD];
__device__ float g_A1[NN * DD];
__device__ float g_H1[NN * DD];
__device__ float g_H2[NN * DD];
__device__ float g_H3[NN * DD];
__device__ int    g_cnt[NN];
__device__ int    g_ptr[NN + 1];
__device__ int    g_esrc[EE];
__device__ double g_stat[3][128];   // per-conv: [0:64) col sums, [64:128) col sumsq

// ---------------- CSR build --------------------------------------------------
__global__ void k_init() {
    int i = blockIdx.x * blockDim.x + threadIdx.x;
    if (i < NN) g_cnt[i] = 0;
    if (i < 3 * 128) ((double*)g_stat)[i] = 0.0;
}

__global__ void k_count(const int* __restrict__ dst) {
    int e = (blockIdx.x * blockDim.x + threadIdx.x) * 2;
    if (e < EE) {
        int2 d = *(const int2*)(dst + e);
        atomicAdd(&g_cnt[d.x], 1);
        atomicAdd(&g_cnt[d.y], 1);
    }
}

__global__ void k_scan() {
    __shared__ int ps[1024];
    int t = threadIdx.x;
    int base = t << 6;
    int s = 0;
#pragma unroll 8
    for (int j = 0; j < 64; j++) s += g_cnt[base + j];
    ps[t] = s;
    __syncthreads();
    for (int off = 1; off < 1024; off <<= 1) {
        int add = 0;
        if (t >= off) add = ps[t - off];
        __syncthreads();
        ps[t] += add;
        __syncthreads();
    }
    int incl = ps[t];
    int run = incl - s;
#pragma unroll 8
    for (int j = 0; j < 64; j++) {
        int c = g_cnt[base + j];
        g_ptr[base + j] = run;
        run += c;
        g_cnt[base + j] = 0;   // reuse as fill cursor in scatter
    }
    if (t == 1023) g_ptr[NN] = incl;
}

__global__ void k_scatter(const int* __restrict__ src, const int* __restrict__ dst) {
    int e = (blockIdx.x * blockDim.x + threadIdx.x) * 2;
    if (e < EE) {
        int2 d = *(const int2*)(dst + e);
        int2 s = *(const int2*)(src + e);
        int p0 = atomicAdd(&g_cnt[d.x], 1);
        g_esrc[g_ptr[d.x] + p0] = s.x;
        int p1 = atomicAdd(&g_cnt[d.y], 1);
        g_esrc[g_ptr[d.y] + p1] = s.y;
    }
}

// ---------------- register-tiled GEMM: 128 rows x 64 cols per block ----------
// 256 threads: tx = t&15 -> 4 cols, ty = t>>4 -> 8 rows. 32 outputs/thread.
// Optional dual weights (two outputs from one input tile), optional BN+ReLU
// applied to the input on load (from g_stat[statIn] + gvec/bvec), optional
// column stats (sum/sumsq) accumulated to g_stat[statOut].
#define MM_AS_STRIDE 66
#define MM_SMEM_FLOATS (128 * MM_AS_STRIDE + 2 * 64 * 64 + 64 + 64 + 64 + 64)

template <int DUAL, int IN_BN, int STATS>
__global__ __launch_bounds__(256) void k_mm(
        const float* __restrict__ in,
        const float* __restrict__ W0, const float* __restrict__ W1,
        float* __restrict__ out0, float* __restrict__ out1,
        const float* __restrict__ gvec, const float* __restrict__ bvec,
        int statIn, int statOut) {
    extern __shared__ float sm[];
    float* As  = sm;                          // 128 x 66
    float* Ws  = As + 128 * MM_AS_STRIDE;     // [2][64][64]
    float* bnS = Ws + 2 * 64 * 64;            // 64
    float* bnB = bnS + 64;                    // 64
    float* ssum = bnB + 64;                   // 64
    float* ssq  = ssum + 64;                  // 64

    int t = threadIdx.x;
    int tx = t & 15, ty = t >> 4;
    int row0 = blockIdx.x * 128;

    // weights
    for (int i = t; i < 4096; i += 256) {
        Ws[i] = W0[i];
        if (DUAL) Ws[4096 + i] = W1[i];
    }
    // BN scale/shift
    if (IN_BN && t < 64) {
        double sum = g_stat[statIn][t];
        double sq  = g_stat[statIn][64 + t];
        double mu_d = sum / (double)NN;
        double var_d = sq / (double)NN - mu_d * mu_d;
        float inv = rsqrtf(fmaxf((float)var_d, 0.f) + BN_EPS);
        float sc = inv * gvec[t];
        bnS[t] = sc;
        bnB[t] = bvec[t] - (float)mu_d * sc;
    }
    if (STATS && t < 64) { ssum[t] = 0.f; ssq[t] = 0.f; }
    if (IN_BN) __syncthreads();   // bnS/bnB ready before A-tile transform

    // A tile (128 x 64), optionally BN+ReLU on load
    {
        const float4* inr = (const float4*)(in + (size_t)row0 * 64);
#pragma unroll
        for (int i = 0; i < 8; i++) {
            int l = i * 256 + t;
            float4 v = inr[l];
            int r = l >> 4;
            int kk = (l & 15) * 4;
            if (IN_BN) {
                v.x = fmaxf(fmaf(v.x, bnS[kk + 0], bnB[kk + 0]), 0.f);
                v.y = fmaxf(fmaf(v.y, bnS[kk + 1], bnB[kk + 1]), 0.f);
                v.z = fmaxf(fmaf(v.z, bnS[kk + 2], bnB[kk + 2]), 0.f);
                v.w = fmaxf(fmaf(v.w, bnS[kk + 3], bnB[kk + 3]), 0.f);
            }
            float* d = As + r * MM_AS_STRIDE + kk;
            d[0] = v.x; d[1] = v.y; d[2] = v.z; d[3] = v.w;
        }
    }
    __syncthreads();

    float acc0[8][4];
    float acc1[8][4];
#pragma unroll
    for (int i = 0; i < 8; i++)
#pragma unroll
        for (int j = 0; j < 4; j++) { acc0[i][j] = 0.f; if (DUAL) acc1[i][j] = 0.f; }

    const float* arow = As + ty * 8 * MM_AS_STRIDE;
#pragma unroll 4
    for (int k = 0; k < 64; k++) {
        float4 w0 = *(const float4*)(Ws + k * 64 + tx * 4);
        float4 w1;
        if (DUAL) w1 = *(const float4*)(Ws + 4096 + k * 64 + tx * 4);
#pragma unroll
        for (int i = 0; i < 8; i++) {
            float a = arow[i * MM_AS_STRIDE + k];
            acc0[i][0] = fmaf(a, w0.x, acc0[i][0]);
            acc0[i][1] = fmaf(a, w0.y, acc0[i][1]);
            acc0[i][2] = fmaf(a, w0.z, acc0[i][2]);
            acc0[i][3] = fmaf(a, w0.w, acc0[i][3]);
            if (DUAL) {
                acc1[i][0] = fmaf(a, w1.x, acc1[i][0]);
                acc1[i][1] = fmaf(a, w1.y, acc1[i][1]);
                acc1[i][2] = fmaf(a, w1.z, acc1[i][2]);
                acc1[i][3] = fmaf(a, w1.w, acc1[i][3]);
            }
        }
    }

    // store
#pragma unroll
    for (int i = 0; i < 8; i++) {
        int row = row0 + ty * 8 + i;
        ((float4*)out0)[row * 16 + tx] =
            make_float4(acc0[i][0], acc0[i][1], acc0[i][2], acc0[i][3]);
        if (DUAL)
            ((float4*)out1)[row * 16 + tx] =
                make_float4(acc1[i][0], acc1[i][1], acc1[i][2], acc1[i][3]);
    }

    if (STATS) {
        float cs[4] = {0.f, 0.f, 0.f, 0.f}, cq[4] = {0.f, 0.f, 0.f, 0.f};
#pragma unroll
        for (int i = 0; i < 8; i++)
#pragma unroll
            for (int j = 0; j < 4; j++) {
                float v = acc0[i][j];
                cs[j] += v;
                cq[j] += v * v;
            }
#pragma unroll
        for (int j = 0; j < 4; j++) {
            atomicAdd(&ssum[tx * 4 + j], cs[j]);
            atomicAdd(&ssq[tx * 4 + j], cq[j]);
        }
        __syncthreads();
        if (t < 64) {
            atomicAdd(&g_stat[statOut][t],      (double)ssum[t]);
            atomicAdd(&g_stat[statOut][64 + t], (double)ssq[t]);
        }
    }
}

// ---------------- gather-max: warp per node, float2 per lane, 4x unroll ------
template <int DUAL>
__global__ void k_gather(const float* __restrict__ y0, const float* __restrict__ y1,
                         const float* __restrict__ pos,
                         const float* __restrict__ Wp0,   // rows 64,65 of Wl
                         const float* __restrict__ Wp1,
                         float* __restrict__ a0out, float* __restrict__ a1out) {
    int warp = threadIdx.x >> 5, lane = threadIdx.x & 31;
    int node = blockIdx.x * 8 + warp;

    const float2* Y0 = (const float2*)y0;
    const float2* Y1 = (const float2*)y1;
    const float2* P  = (const float2*)pos;

    float2 wx0 = ((const float2*)Wp0)[lane];
    float2 wy0 = ((const float2*)(Wp0 + 64))[lane];
    float2 wx1 = make_float2(0.f, 0.f), wy1 = make_float2(0.f, 0.f);
    if (DUAL) {
        wx1 = ((const float2*)Wp1)[lane];
        wy1 = ((const float2*)(Wp1 + 64))[lane];
    }

    float2 pi = P[node];
    float2 m0 = Y0[node * 32 + lane];               // self-loop (dpos = 0)
    float2 m1 = make_float2(0.f, 0.f);
    if (DUAL) m1 = Y1[node * 32 + lane];

    int b = g_ptr[node], e = g_ptr[node + 1];
    int k = b;
    for (; k + 4 <= e; k += 4) {
        int s0 = g_esrc[k + 0];
        int s1 = g_esrc[k + 1];
        int s2 = g_esrc[k + 2];
        int s3 = g_esrc[k + 3];
        float2 p0 = P[s0], p1 = P[s1], p2 = P[s2], p3 = P[s3];
        float2 v0 = Y0[s0 * 32 + lane];
        float2 v1 = Y0[s1 * 32 + lane];
        float2 v2 = Y0[s2 * 32 + lane];
        float2 v3 = Y0[s3 * 32 + lane];
        float dx0 = p0.x - pi.x, dy0 = p0.y - pi.y;
        float dx1 = p1.x - pi.x, dy1 = p1.y - pi.y;
        float dx2 = p2.x - pi.x, dy2 = p2.y - pi.y;
        float dx3 = p3.x - pi.x, dy3 = p3.y - pi.y;
        v0.x = fmaf(dx0, wx0.x, fmaf(dy0, wy0.x, v0.x));
        v0.y = fmaf(dx0, wx0.y, fmaf(dy0, wy0.y, v0.y));
        v1.x = fmaf(dx1, wx0.x, fmaf(dy1, wy0.x, v1.x));
        v1.y = fmaf(dx1, wx0.y, fmaf(dy1, wy0.y, v1.y));
        v2.x = fmaf(dx2, wx0.x, fmaf(dy2, wy0.x, v2.x));
        v2.y = fmaf(dx2, wx0.y, fmaf(dy2, wy0.y, v2.y));
        v3.x = fmaf(dx3, wx0.x, fmaf(dy3, wy0.x, v3.x));
        v3.y = fmaf(dx3, wx0.y, fmaf(dy3, wy0.y, v3.y));
        m0.x = fmaxf(m0.x, fmaxf(fmaxf(v0.x, v1.x), fmaxf(v2.x, v3.x)));
        m0.y = fmaxf(m0.y, fmaxf(fmaxf(v0.y, v1.y), fmaxf(v2.y, v3.y)));
        if (DUAL) {
            float2 u0 = Y1[s0 * 32 + lane];
            float2 u1 = Y1[s1 * 32 + lane];
            float2 u2 = Y1[s2 * 32 + lane];
            float2 u3 = Y1[s3 * 32 + lane];
            u0.x = fmaf(dx0, wx1.x, fmaf(dy0, wy1.x, u0.x));
            u0.y = fmaf(dx0, wx1.y, fmaf(dy0, wy1.y, u0.y));
            u1.x = fmaf(dx1, wx1.x, fmaf(dy1, wy1.x, u1.x));
            u1.y = fmaf(dx1, wx1.y, fmaf(dy1, wy1.y, u1.y));
            u2.x = fmaf(dx2, wx1.x, fmaf(dy2, wy1.x, u2.x));
            u2.y = fmaf(dx2, wx1.y, fmaf(dy2, wy1.y, u2.y));
            u3.x = fmaf(dx3, wx1.x, fmaf(dy3, wy1.x, u3.x));
            u3.y = fmaf(dx3, wx1.y, fmaf(dy3, wy1.y, u3.y));
            m1.x = fmaxf(m1.x, fmaxf(fmaxf(u0.x, u1.x), fmaxf(u2.x, u3.x)));
            m1.y = fmaxf(m1.y, fmaxf(fmaxf(u0.y, u1.y), fmaxf(u2.y, u3.y)));
        }
    }
    for (; k < e; k++) {
        int s = g_esrc[k];
        float2 psrc = P[s];
        float dx = psrc.x - pi.x, dy = psrc.y - pi.y;
        float2 v = Y0[s * 32 + lane];
        v.x = fmaf(dx, wx0.x, fmaf(dy, wy0.x, v.x));
        v.y = fmaf(dx, wx0.y, fmaf(dy, wy0.y, v.y));
        m0.x = fmaxf(m0.x, v.x);
        m0.y = fmaxf(m0.y, v.y);
        if (DUAL) {
            float2 u = Y1[s * 32 + lane];
            u.x = fmaf(dx, wx1.x, fmaf(dy, wy1.x, u.x));
            u.y = fmaf(dx, wx1.y, fmaf(dy, wy1.y, u.y));
            m1.x = fmaxf(m1.x, u.x);
            m1.y = fmaxf(m1.y, u.y);
        }
    }
    ((float2*)a0out)[node * 32 + lane] = m0;
    if (DUAL) ((float2*)a1out)[node * 32 + lane] = m1;
}

// ---------------- cls head: 128 rows x 101 cols, register tiled --------------
// 512 threads: tx = t&31 -> 4 cols (of 128 padded), ty = t>>5 -> 8 rows.
#define HD_SMEM_FLOATS (128 * MM_AS_STRIDE + 64 * 128 + 128)

__global__ __launch_bounds__(512) void k_head101(
        const float* __restrict__ in, const float* __restrict__ W,
        const float* __restrict__ bias, float* __restrict__ out) {
    extern __shared__ float sm[];
    float* As = sm;                        // 128 x 66
    float* Ws = As + 128 * MM_AS_STRIDE;   // 64 x 128 (zero-padded)
    float* bS = Ws + 64 * 128;             // 128

    int t = threadIdx.x;
    int tx = t & 31, ty = t >> 5;
    int row0 = blockIdx.x * 128;

    for (int i = t; i < 64 * 128; i += 512) {
        int k = i >> 7, c = i & 127;
        Ws[i] = (c < CC) ? W[k * CC + c] : 0.f;
    }
    if (t < 128) bS[t] = (t < CC) ? bias[t] : 0.f;

    {
        const float4* inr = (const float4*)(in + (size_t)row0 * 64);
#pragma unroll
        for (int i = 0; i < 4; i++) {
            int l = i * 512 + t;
            float4 v = inr[l];
            int r = l >> 4;
            int kk = (l & 15) * 4;
            float* d = As + r * MM_AS_STRIDE + kk;
            d[0] = v.x; d[1] = v.y; d[2] = v.z; d[3] = v.w;
        }
    }
    __syncthreads();

    float acc[8][4];
#pragma unroll
    for (int i = 0; i < 8; i++)
#pragma unroll
        for (int j = 0; j < 4; j++) acc[i][j] = 0.f;

    const float* arow = As + ty * 8 * MM_AS_STRIDE;
#pragma unroll 4
    for (int k = 0; k < 64; k++) {
        float4 w = *(const float4*)(Ws + k * 128 + tx * 4);
#pragma unroll
        for (int i = 0; i < 8; i++) {
            float a = arow[i * MM_AS_STRIDE + k];
            acc[i][0] = fmaf(a, w.x, acc[i][0]);
            acc[i][1] = fmaf(a, w.y, acc[i][1]);
            acc[i][2] = fmaf(a, w.z, acc[i][2]);
            acc[i][3] = fmaf(a, w.w, acc[i][3]);
        }
    }

#pragma unroll
    for (int i = 0; i < 8; i++) {
        int row = row0 + ty * 8 + i;
#pragma unroll
        for (int j = 0; j < 4; j++) {
            int col = tx * 4 + j;
            if (col < CC) out[(size_t)row * CC + col] = acc[i][j] + bS[col];
        }
    }
}

// ---------------- small head GEMM (K = 4, 1): warp per row, shuffle ----------
template <int K>
__global__ void k_head(const float* __restrict__ in, const float* __restrict__ W,
                       const float* __restrict__ bias, float* __restrict__ out) {
    __shared__ float Ws[64 * K];
    int t = threadIdx.x;
    for (int i = t; i < 64 * K; i += blockDim.x) Ws[i] = W[i];
    __syncthreads();
    int warp = t >> 5, lane = t & 31;
    int row = blockIdx.x * 8 + warp;
    constexpr int NC = (K + 31) / 32;
    float acc[NC];
#pragma unroll
    for (int c = 0; c < NC; c++) {
        int col = lane + 32 * c;
        acc[c] = (col < K) ? bias[col] : 0.f;
    }
    float r0v = in[row * 64 + lane];
    float r1v = in[row * 64 + 32 + lane];
#pragma unroll
    for (int j = 0; j < 32; j++) {
        float v = __shfl_sync(0xffffffffu, r0v, j);
#pragma unroll
        for (int c = 0; c < NC; c++) {
            int col = lane + 32 * c;
            if (col < K) acc[c] = fmaf(v, Ws[j * K + col], acc[c]);
        }
    }
#pragma unroll
    for (int j = 0; j < 32; j++) {
        float v = __shfl_sync(0xffffffffu, r1v, j);
#pragma unroll
        for (int c = 0; c < NC; c++) {
            int col = lane + 32 * c;
            if (col < K) acc[c] = fmaf(v, Ws[(32 + j) * K + col], acc[c]);
        }
    }
#pragma unroll
    for (int c = 0; c < NC; c++) {
        int col = lane + 32 * c;
        if (col < K) out[row * K + col] = acc[c];
    }
}

// ---------------- launch -----------------------------------------------------
extern "C" void kernel_launch(void* const* d_in, const int* in_sizes, int n_in,
                              void* d_out, int out_size) {
    const float* x   = (const float*)d_in[0];
    const float* pos = (const float*)d_in[1];
    const int*   ei  = (const int*)  d_in[2];
    const float* W11 = (const float*)d_in[3];
    const float* W12 = (const float*)d_in[4];
    const float* g1  = (const float*)d_in[5];
    const float* b1  = (const float*)d_in[6];
    const float* W21 = (const float*)d_in[7];
    const float* W22 = (const float*)d_in[8];
    const float* g2  = (const float*)d_in[9];
    const float* b2  = (const float*)d_in[10];
    const float* W31 = (const float*)d_in[11];
    const float* W32 = (const float*)d_in[12];
    const float* g3  = (const float*)d_in[13];
    const float* b3  = (const float*)d_in[14];
    const float* Wr1 = (const float*)d_in[15];
    const float* Wr2 = (const float*)d_in[16];
    const float* br2 = (const float*)d_in[17];
    const float* Wc1 = (const float*)d_in[18];
    const float* Wc2 = (const float*)d_in[19];
    const float* bc2 = (const float*)d_in[20];
    const float* Wo1 = (const float*)d_in[21];
    const float* Wo2 = (const float*)d_in[22];
    const float* bo2 = (const float*)d_in[23];
    float* out = (float*)d_out;

    float* out_cls = out;                      // N x 101
    float* out_reg = out + (size_t)NN * CC;    // N x 4
    float* out_obj = out_reg + (size_t)NN * 4; // N x 1

    const int* src = ei;
    const int* dst = ei + EE;

    float *Y0, *Y1, *A0, *A1, *H1, *H2, *H3;
    cudaGetSymbolAddress((void**)&Y0, g_Y0);
    cudaGetSymbolAddress((void**)&Y1, g_Y1);
    cudaGetSymbolAddress((void**)&A0, g_A0);
    cudaGetSymbolAddress((void**)&A1, g_A1);
    cudaGetSymbolAddress((void**)&H1, g_H1);
    cudaGetSymbolAddress((void**)&H2, g_H2);
    cudaGetSymbolAddress((void**)&H3, g_H3);

    const int MM_SMEM = MM_SMEM_FLOATS * 4;
    const int HD_SMEM = HD_SMEM_FLOATS * 4;
    cudaFuncSetAttribute(k_mm<0, 0, 0>, cudaFuncAttributeMaxDynamicSharedMemorySize, MM_SMEM);
    cudaFuncSetAttribute(k_mm<0, 0, 1>, cudaFuncAttributeMaxDynamicSharedMemorySize, MM_SMEM);
    cudaFuncSetAttribute(k_mm<0, 1, 0>, cudaFuncAttributeMaxDynamicSharedMemorySize, MM_SMEM);
    cudaFuncSetAttribute(k_mm<1, 1, 0>, cudaFuncAttributeMaxDynamicSharedMemorySize, MM_SMEM);
    cudaFuncSetAttribute(k_head101,     cudaFuncAttributeMaxDynamicSharedMemorySize, HD_SMEM);

    const int TB = 256;

    // ---- CSR build
    k_init<<<(NN + TB - 1) / TB, TB>>>();
    k_count<<<EE / (2 * TB), TB>>>(dst);
    k_scan<<<1, 1024>>>();
    k_scatter<<<EE / (2 * TB), TB>>>(src, dst);

    const int GM = NN / 128;    // k_mm / k_head101 grid
    const int GG = NN / 8;      // gather / small-head grid

    // ---- conv1: x -> (bn1-fused later)
    k_mm<0, 0, 0><<<GM, TB, MM_SMEM>>>(x, W11, nullptr, Y0, nullptr, nullptr, nullptr, 0, 0);
    k_gather<0><<<GG, TB>>>(Y0, Y0, pos, W11 + 64 * 64, W11 + 64 * 64, A0, A0);
    k_mm<0, 0, 1><<<GM, TB, MM_SMEM>>>(A0, W12, nullptr, H1, nullptr, nullptr, nullptr, 0, 0);

    // ---- conv2 + conv3 (shared input relu(bn1(H1)), fused)
    k_mm<1, 1, 0><<<GM, TB, MM_SMEM>>>(H1, W21, W31, Y0, Y1, g1, b1, 0, 0);
    k_gather<1><<<GG, TB>>>(Y0, Y1, pos, W21 + 64 * 64, W31 + 64 * 64, A0, A1);
    k_mm<0, 0, 1><<<GM, TB, MM_SMEM>>>(A0, W22, nullptr, H2, nullptr, nullptr, nullptr, 0, 1);
    k_mm<0, 0, 1><<<GM, TB, MM_SMEM>>>(A1, W32, nullptr, H3, nullptr, nullptr, nullptr, 0, 2);

    // ---- reg head (from relu(bn2(H2)))
    k_mm<0, 1, 0><<<GM, TB, MM_SMEM>>>(H2, Wr1, nullptr, Y0, nullptr, g2, b2, 1, 0);
    k_gather<0><<<GG, TB>>>(Y0, Y0, pos, Wr1 + 64 * 64, Wr1 + 64 * 64, A0, A0);
    k_head<4><<<GG, TB>>>(A0, Wr2, br2, out_reg);

    // ---- cls + obj heads (shared input relu(bn3(H3)), fused)
    k_mm<1, 1, 0><<<GM, TB, MM_SMEM>>>(H3, Wc1, Wo1, Y0, Y1, g3, b3, 2, 0);
    k_gather<1><<<GG, TB>>>(Y0, Y1, pos, Wc1 + 64 * 64, Wo1 + 64 * 64, A0, A1);
    k_head101<<<GM, 512, HD_SMEM>>>(A0, Wc2, bc2, out_cls);
    k_head<1><<<GG, TB>>>(A1, Wo2, bo2, out_obj);
}